// round 12
// baseline (speedup 1.0000x reference)
#include <cuda_runtime.h>
#include <math.h>

#define IMG   512
#define NPIX  (IMG*IMG)
#define NB    4
#define NO    6
#define NL    4
#define TILE  64
#define TS    71      // centered extent (rows & cols)
#define BCS   76      // BC/AC stride: conflict-free float4 rows
#define XR    78      // raw tile rows/cols
#define XS2   84      // raw tile stride: conflict-free float4
#define HMS   76      // Hm stride
#define HS    68      // H box-buffer stride: cf float4, 16B aligned
#define EPS   1e-20f
#define NT    1024
#define NCTA  (8*8*NB)   // 256

// sizes in floats (all multiples of 4)
#define SZ_BC   (TS*BCS)       // 5396
#define SZ_X    (XR*XS2)       // 6552
#define SZ_HM   (XR*HMS)       // 5928
#define SZ_HB   (TS*HS)        // 4828
#define R_FLOATS (5*SZ_HB)     // 24140 (hosts Hm transiently; Hm dead before H written)
#define SMEM_FLOATS (NL*SZ_BC + SZ_BC + R_FLOATS + SZ_X)   // 57672 -> 230,688 B

__device__ float d_partial[NB*NO*64];
__device__ unsigned int d_count = 0;

// ---- depth-3 tree: o[k] = sum_{d=0..7} w[k+d], k=0..7, from w[0..14] ----
__device__ __forceinline__ void win8_tree(const float* w, float* o) {
    float p2[14];
    #pragma unroll
    for (int i = 0; i < 14; i++) p2[i] = w[i] + w[i+1];
    float p4[12];
    #pragma unroll
    for (int i = 0; i < 12; i++) p4[i] = p2[i] + p2[i+2];
    #pragma unroll
    for (int k = 0; k < 8; k++) o[k] = p4[k] + p4[k+4];
}

// ---- load raw 78x78 tile (zero outside image), plain scalar LDG ----
__device__ __forceinline__ void load_tile(const float* __restrict__ src, float* __restrict__ X,
                                          int tx0, int ty0, int tid) {
    for (int idx = tid; idx < XR*XR; idx += NT) {
        int r = idx / XR, c = idx % XR;
        int gr = ty0 + r - 6, gc = tx0 + c - 6;
        float v = 0.f;
        if ((unsigned)gr < (unsigned)IMG && (unsigned)gc < (unsigned)IMG)
            v = __ldg(src + gr*IMG + gc);
        X[r*XS2 + c] = v;
    }
}

// ---- Hm[r][c] = sum_{d=0..7} X[r][c+d], r<78, c<71 ; float4 in/out ----
__device__ __forceinline__ void hmean(const float* __restrict__ X, float* __restrict__ Hm, int tid) {
    for (int idx = tid; idx < XR*9; idx += NT) {
        int r = idx % XR, q = idx / XR;
        int c0 = q * 8;                                   // 0..64
        const float4* xp = (const float4*)(X + r*XS2 + c0);
        float4 v0 = xp[0], v1 = xp[1], v2 = xp[2], v3 = xp[3];
        float w[15] = {v0.x,v0.y,v0.z,v0.w, v1.x,v1.y,v1.z,v1.w,
                       v2.x,v2.y,v2.z,v2.w, v3.x,v3.y,v3.z};
        float o[8];
        win8_tree(w, o);
        float4* hp = (float4*)(Hm + r*HMS + c0);
        hp[0] = make_float4(o[0],o[1],o[2],o[3]);
        hp[1] = make_float4(o[4],o[5],o[6],o[7]);
    }
}

// ---- OUT[r][c] = inside ? X[r+3][c+3] - boxmean : 0, r,c<71 ----
__device__ __forceinline__ void centered(const float* __restrict__ X, const float* __restrict__ Hm,
                                         float* __restrict__ OUT, int tx0, int ty0, int tid) {
    for (int idx = tid; idx < TS*9; idx += NT) {
        int c = idx % TS, q = idx / TS;
        int r0 = q * 8;
        int cnt = min(8, TS - r0);
        float h[15];
        #pragma unroll
        for (int d = 0; d < 15; d++) h[d] = Hm[min(r0 + d, XR-1)*HMS + c];
        float xv[8];
        #pragma unroll
        for (int k = 0; k < 8; k++) xv[k] = X[(r0 + k + 3)*XS2 + (c + 3)];
        float o[8];
        win8_tree(h, o);
        int gc = tx0 + c - 3;
        bool cin = (unsigned)gc < (unsigned)IMG;
        #pragma unroll
        for (int k = 0; k < 8; k++) {
            if (k < cnt) {
                int r = r0 + k;
                int gr = ty0 + r - 3;
                float v = 0.f;
                if (cin && (unsigned)gr < (unsigned)IMG) v = xv[k] - o[k] * (1.f/64.f);
                OUT[r*BCS + c] = v;
            }
        }
    }
}

// ---- tree window-sum of w[0..14] -> 8 outputs, float4-stored ----
__device__ __forceinline__ void prefix_store(const float* w, float* __restrict__ hr) {
    float o[8];
    win8_tree(w, o);
    float4* hp = (float4*)hr;
    hp[0] = make_float4(o[0],o[1],o[2],o[3]);
    hp[1] = make_float4(o[4],o[5],o[6],o[7]);
}

// ---- 4 vertical window sums of Hb at column cl, row group g (tree) ----
__device__ __forceinline__ void vsum4(const float* __restrict__ Hb, int g, int cl, float* out) {
    float h[11];
    #pragma unroll
    for (int k = 0; k < 11; k++) h[k] = Hb[(g*4 + k)*HS + cl];
    float p2[10];
    #pragma unroll
    for (int i = 0; i < 10; i++) p2[i] = h[i] + h[i+1];
    float p4[8];
    #pragma unroll
    for (int i = 0; i < 8; i++) p4[i] = p2[i] + p2[i+2];
    #pragma unroll
    for (int k = 0; k < 4; k++) out[k] = p4[k] + p4[k+4];
}

// =========================================================================
// fused: one CTA per (batch, 64x64 tile), 1024 threads, finalize in-kernel.
// =========================================================================
__global__ void __launch_bounds__(NT, 1)
fused_kernel(const float* __restrict__ outs, const float* __restrict__ labs,
             float* __restrict__ out, int out_size) {
    extern __shared__ float sm[];
    float* BC = sm;                  // NL * 5396
    float* AC = BC + NL*SZ_BC;       // 5396
    float* R  = AC + SZ_BC;          // 24140: Hm (transient) / H0..H4
    float* Hm = R;                   // 5928 (dead before H written)
    float* X  = R + R_FLOATS;        // 6552 DEDICATED raw-tile buffer
    __shared__ float s_red[NO*32];
    __shared__ unsigned int s_flag;
    __shared__ float s_vals[NB*NO];

    int tx0 = blockIdx.x * TILE, ty0 = blockIdx.y * TILE;
    int b = blockIdx.z;
    int tid = threadIdx.x;
    int cl = tid & 63, g = tid >> 6;      // pixel column / row-group (g 0..15, 4 rows)
    int lane = tid & 31, wid = tid >> 5;

    // ---------------- phase 1: labels -> BC[l] ----------------
    for (int l = 0; l < NL; l++) {
        load_tile(labs + (size_t)(b*NL + l)*NPIX, X, tx0, ty0, tid);
        __syncthreads();
        hmean(X, Hm, tid);
        __syncthreads();
        centered(X, Hm, BC + l*SZ_BC, tx0, ty0, tid);
        __syncthreads();                  // BC[l] ready; X/Hm readers retired
    }

    // fused sjj phase: box-row sums of bc_l^2 for all 4 labels -> H0..H3 (568 items)
    for (int idx = tid; idx < TS*8; idx += NT) {
        int r = idx % TS, q = idx / TS;
        int c0 = q * 8;
        #pragma unroll
        for (int l = 0; l < NL; l++) {
            const float4* bp = (const float4*)(BC + l*SZ_BC + r*BCS + c0);
            float4 v0 = bp[0], v1 = bp[1], v2 = bp[2], v3 = bp[3];
            float bb[15] = {v0.x,v0.y,v0.z,v0.w, v1.x,v1.y,v1.z,v1.w,
                            v2.x,v2.y,v2.z,v2.w, v3.x,v3.y,v3.z};
            float w[15];
            #pragma unroll
            for (int d = 0; d < 15; d++) w[d] = bb[d]*bb[d];
            prefix_store(w, R + l*SZ_HB + r*HS + c0);
        }
    }
    __syncthreads();

    float rsjjR[NL][4];
    #pragma unroll
    for (int l = 0; l < NL; l++) {
        float v4[4];
        vsum4(R + l*SZ_HB, g, cl, v4);
        #pragma unroll
        for (int k = 0; k < 4; k++) rsjjR[l][k] = rsqrtf(fmaxf(v4[k], EPS));
    }
    // o-loop head barrier orders these R reads before hmean overwrites R

    // ---------------- phase 2: outputs ----------------
    for (int o = 0; o < NO; o++) {
        load_tile(outs + (size_t)(b*NO + o)*NPIX, X, tx0, ty0, tid);  // X disjoint from R
        __syncthreads();                  // (1) X visible; retires prior R/vsum readers
        hmean(X, Hm, tid);
        __syncthreads();                  // (2)
        centered(X, Hm, AC, tx0, ty0, tid);
        __syncthreads();                  // (3) AC ready; Hm dead -> R hosts H0..H4

        // fused hprod: ac window loaded once; j=0 -> ac*ac, j=1..4 -> ac*bc_{j-1}
        for (int idx = tid; idx < TS*8; idx += NT) {
            int r = idx % TS, q = idx / TS;
            int c0 = q * 8;
            const float4* ap = (const float4*)(AC + r*BCS + c0);
            float4 a0 = ap[0], a1 = ap[1], a2 = ap[2], a3 = ap[3];
            float a[15] = {a0.x,a0.y,a0.z,a0.w, a1.x,a1.y,a1.z,a1.w,
                           a2.x,a2.y,a2.z,a2.w, a3.x,a3.y,a3.z};
            {
                float w[15];
                #pragma unroll
                for (int d = 0; d < 15; d++) w[d] = a[d]*a[d];
                prefix_store(w, R + r*HS + c0);
            }
            #pragma unroll
            for (int l = 0; l < NL; l++) {
                const float4* bp = (const float4*)(BC + l*SZ_BC + r*BCS + c0);
                float4 u0 = bp[0], u1 = bp[1], u2 = bp[2], u3 = bp[3];
                float bb[15] = {u0.x,u0.y,u0.z,u0.w, u1.x,u1.y,u1.z,u1.w,
                                u2.x,u2.y,u2.z,u2.w, u3.x,u3.y,u3.z};
                float w[15];
                #pragma unroll
                for (int d = 0; d < 15; d++) w[d] = a[d]*bb[d];
                prefix_store(w, R + (l+1)*SZ_HB + r*HS + c0);
            }
        }
        __syncthreads();                  // (4) H0..H4 ready

        float rsii[4];
        {
            float v4[4];
            vsum4(R, g, cl, v4);
            #pragma unroll
            for (int k = 0; k < 4; k++) rsii[k] = rsqrtf(fmaxf(v4[k], EPS));
        }

        float maxcc[4];
        #pragma unroll
        for (int k = 0; k < 4; k++) maxcc[k] = -1.0f;

        #pragma unroll
        for (int l = 0; l < NL; l++) {
            float sij4[4];
            vsum4(R + (l+1)*SZ_HB, g, cl, sij4);
            #pragma unroll
            for (int k = 0; k < 4; k++) {
                float cc = sij4[k] * (rsii[k] * rsjjR[l][k]);
                maxcc[k] = fmaxf(maxcc[k], cc);
            }
        }

        float local = 0.f;
        #pragma unroll
        for (int k = 0; k < 4; k++) local += 1.0f - fminf(1.0f, maxcc[k]);
        #pragma unroll
        for (int off = 16; off > 0; off >>= 1)
            local += __shfl_down_sync(0xFFFFFFFFu, local, off);
        if (lane == 0) s_red[o*32 + wid] = local;   // deferred: no tail barrier
        // next loop-head barrier (1) orders the R reads above before hmean rewrites R
    }

    // ---------------- deferred per-output reduction ----------------
    __syncthreads();
    if (wid < NO) {
        float v = s_red[wid*32 + lane];
        #pragma unroll
        for (int off = 16; off > 0; off >>= 1)
            v += __shfl_down_sync(0xFFFFFFFFu, v, off);
        if (lane == 0)
            d_partial[(b*NO + wid)*64 + blockIdx.y*8 + blockIdx.x] = v;
    }
    __syncthreads();

    // ---------------- in-kernel finalize (last CTA, fixed-order sums) ------
    if (tid == 0) {
        __threadfence();
        unsigned int v = atomicAdd(&d_count, 1u);
        s_flag = (v == NCTA - 1) ? 1u : 0u;
    }
    __syncthreads();
    if (s_flag) {
        __threadfence();   // acquire: all CTAs' d_partial visible
        if (tid < NB*NO) {
            float s = 0.f;
            for (int i = 0; i < 64; i++) s += d_partial[tid*64 + i];
            float m = s * (1.0f / (float)NPIX);
            s_vals[tid] = m;
            if (1 + tid < out_size) out[1 + tid] = m;
        }
        __syncthreads();
        if (tid == 0) {
            float s = 0.f;
            #pragma unroll
            for (int i = 0; i < NB*NO; i++) s += s_vals[i];
            if (out_size > 0) out[0] = s / (float)(NB*NO);
            d_count = 0;   // reset for next graph replay
        }
    }
}

extern "C" void kernel_launch(void* const* d_in, const int* in_sizes, int n_in,
                              void* d_out, int out_size) {
    const float* outs = (const float*)d_in[0];
    const float* labs = (const float*)d_in[1];
    if (n_in >= 2 && in_sizes[0] < in_sizes[1]) {  // defensive: outputs is larger
        const float* tmp = outs; outs = labs; labs = tmp;
    }

    const int SMEM = SMEM_FLOATS * (int)sizeof(float);   // 230,688 B
    cudaFuncSetAttribute(fused_kernel, cudaFuncAttributeMaxDynamicSharedMemorySize, SMEM);
    fused_kernel<<<dim3(8, 8, NB), NT, SMEM>>>(outs, labs, (float*)d_out, out_size);
}

// round 13
// speedup vs baseline: 1.0968x; 1.0968x over previous
#include <cuda_runtime.h>
#include <math.h>

#define IMG   512
#define NPIX  (IMG*IMG)
#define NB    4
#define NO    6
#define NL    4
#define TILE  64
#define TS    71      // centered extent (rows & cols)
#define BCS   76      // BC/AC stride: conflict-free float4 rows
#define XR    78      // raw tile rows/cols
#define XS2   84      // raw tile stride: conflict-free float4
#define HMS   76      // Hm stride
#define HS    68      // H box-buffer stride: cf float4, 16B aligned
#define EPS   1e-20f
#define NT    1024
#define NCTA  (8*8*NB)   // 256

// sizes in floats (all multiples of 4)
#define SZ_BC   (TS*BCS)       // 5396
#define SZ_X    (XR*XS2)       // 6552
#define SZ_HM   (XR*HMS)       // 5928
#define SZ_HB   (TS*HS)        // 4828
#define R_FLOATS (5*SZ_HB)     // 24140 (hosts Hm transiently; Hm dead before H written)
#define SMEM_FLOATS (NL*SZ_BC + SZ_BC + R_FLOATS + SZ_X)   // 57672 -> 230,688 B

__device__ float d_partial[NB*NO*64];
__device__ unsigned int d_count = 0;

// ---- load raw 78x78 tile; shift/mask decode, 16 threads per row ----
template<bool IN>
__device__ __forceinline__ void load_tile(const float* __restrict__ src, float* __restrict__ X,
                                          int tx0, int ty0, int tid) {
    int ln = tid & 15, rg = tid >> 4;        // 64 row-threads cover rows, 2 passes
    #pragma unroll
    for (int p = 0; p < 2; p++) {
        int r = rg + 64*p;
        if (p == 0 || rg < XR - 64) {
            int gr = ty0 + r - 6;
            float* xrow = X + r*XS2;
            if (IN) {
                const float* srow = src + gr*IMG + tx0 - 6;
                #pragma unroll
                for (int k = 0; k < 5; k++) {
                    int c = ln + 16*k;
                    if (k < 4 || c < XR) xrow[c] = __ldg(srow + c);
                }
            } else {
                bool rin = (unsigned)gr < (unsigned)IMG;
                #pragma unroll
                for (int k = 0; k < 5; k++) {
                    int c = ln + 16*k;
                    if (k < 4 || c < XR) {
                        int gc = tx0 + c - 6;
                        float v = 0.f;
                        if (rin && (unsigned)gc < (unsigned)IMG)
                            v = __ldg(src + gr*IMG + gc);
                        xrow[c] = v;
                    }
                }
            }
        }
    }
}

// ---- Hm[r][c] = sum_{d=0..7} X[r][c+d], r<78, c<71 ; float4 in/out ----
__device__ __forceinline__ void hmean(const float* __restrict__ X, float* __restrict__ Hm, int tid) {
    for (int idx = tid; idx < XR*9; idx += NT) {
        int r = idx % XR, q = idx / XR;
        int c0 = q * 8;                                   // 0..64
        const float4* xp = (const float4*)(X + r*XS2 + c0);
        float4 v0 = xp[0], v1 = xp[1], v2 = xp[2], v3 = xp[3];
        float w[16] = {v0.x,v0.y,v0.z,v0.w, v1.x,v1.y,v1.z,v1.w,
                       v2.x,v2.y,v2.z,v2.w, v3.x,v3.y,v3.z,v3.w};
        float o[8];
        float s = w[0]+w[1]+w[2]+w[3]+w[4]+w[5]+w[6]+w[7];
        o[0] = s;
        #pragma unroll
        for (int k = 1; k < 8; k++) { s += w[k+7] - w[k-1]; o[k] = s; }
        float4* hp = (float4*)(Hm + r*HMS + c0);
        hp[0] = make_float4(o[0],o[1],o[2],o[3]);
        hp[1] = make_float4(o[4],o[5],o[6],o[7]);
    }
}

// ---- OUT[r][c] = inside ? X[r+3][c+3] - boxmean : 0, r,c<71 ----
template<bool IN>
__device__ __forceinline__ void centered(const float* __restrict__ X, const float* __restrict__ Hm,
                                         float* __restrict__ OUT, int tx0, int ty0, int tid) {
    for (int idx = tid; idx < TS*9; idx += NT) {
        int c = idx % TS, q = idx / TS;
        int r0 = q * 8;
        int cnt = min(8, TS - r0);
        float h[15];
        #pragma unroll
        for (int d = 0; d < 15; d++) h[d] = Hm[min(r0 + d, XR-1)*HMS + c];
        float xv[8];
        #pragma unroll
        for (int k = 0; k < 8; k++) xv[k] = X[(r0 + k + 3)*XS2 + (c + 3)];
        float s = h[0]+h[1]+h[2]+h[3]+h[4]+h[5]+h[6]+h[7];
        bool cin = IN || ((unsigned)(tx0 + c - 3) < (unsigned)IMG);
        #pragma unroll
        for (int k = 0; k < 8; k++) {
            if (k < cnt) {
                int r = r0 + k;
                float v;
                if (IN) {
                    v = xv[k] - s * (1.f/64.f);
                } else {
                    int gr = ty0 + r - 3;
                    v = 0.f;
                    if (cin && (unsigned)gr < (unsigned)IMG) v = xv[k] - s * (1.f/64.f);
                }
                OUT[r*BCS + c] = v;
                if (k + 1 < cnt) s += h[k+8] - h[k];
            }
        }
    }
}

// ---- running window-sum of w[0..14] -> 8 outputs, float4-stored ----
__device__ __forceinline__ void prefix_store(const float* w, float* __restrict__ hr) {
    float o[8];
    float s = w[0]+w[1]+w[2]+w[3]+w[4]+w[5]+w[6]+w[7];
    o[0] = s;
    #pragma unroll
    for (int k = 1; k < 8; k++) { s += w[k+7] - w[k-1]; o[k] = s; }
    float4* hp = (float4*)hr;
    hp[0] = make_float4(o[0],o[1],o[2],o[3]);
    hp[1] = make_float4(o[4],o[5],o[6],o[7]);
}

// ---- 4 vertical window sums of Hb at column cl, row group g ----
__device__ __forceinline__ void vsum4(const float* __restrict__ Hb, int g, int cl, float* out) {
    float ps[12];
    ps[0] = 0.f;
    #pragma unroll
    for (int k = 0; k < 11; k++) ps[k+1] = ps[k] + Hb[(g*4 + k)*HS + cl];
    #pragma unroll
    for (int k = 0; k < 4; k++) out[k] = ps[k+8] - ps[k];
}

// =========================================================================
// fused: one CTA per (batch, 64x64 tile), 1024 threads, finalize in-kernel.
// =========================================================================
__global__ void __launch_bounds__(NT, 1)
fused_kernel(const float* __restrict__ outs, const float* __restrict__ labs,
             float* __restrict__ out, int out_size) {
    extern __shared__ float sm[];
    float* BC = sm;                  // NL * 5396
    float* AC = BC + NL*SZ_BC;       // 5396
    float* R  = AC + SZ_BC;          // 24140: Hm (transient) / H0..H4
    float* Hm = R;                   // 5928 (dead before H written)
    float* X  = R + R_FLOATS;        // 6552 DEDICATED raw-tile buffer
    __shared__ float s_red[NO*32];
    __shared__ unsigned int s_flag;
    __shared__ float s_vals[NB*NO];

    int tx0 = blockIdx.x * TILE, ty0 = blockIdx.y * TILE;
    int b = blockIdx.z;
    int tid = threadIdx.x;
    int cl = tid & 63, g = tid >> 6;      // pixel column / row-group (g 0..15, 4 rows)
    int lane = tid & 31, wid = tid >> 5;
    // interior tiles touch no image border anywhere (rows/cols -6..71 in range)
    const bool interior = (blockIdx.x >= 1 && blockIdx.x <= 6 &&
                           blockIdx.y >= 1 && blockIdx.y <= 6);

    // ---------------- phase 1: labels -> BC[l] ----------------
    for (int l = 0; l < NL; l++) {
        const float* src = labs + (size_t)(b*NL + l)*NPIX;
        if (interior) load_tile<true>(src, X, tx0, ty0, tid);
        else          load_tile<false>(src, X, tx0, ty0, tid);
        __syncthreads();
        hmean(X, Hm, tid);
        __syncthreads();
        if (interior) centered<true>(X, Hm, BC + l*SZ_BC, tx0, ty0, tid);
        else          centered<false>(X, Hm, BC + l*SZ_BC, tx0, ty0, tid);
        __syncthreads();                  // BC[l] ready; X/Hm readers retired
    }

    // fused sjj phase: box-row sums of bc_l^2 for all 4 labels -> H0..H3 (568 items)
    for (int idx = tid; idx < TS*8; idx += NT) {
        int r = idx % TS, q = idx / TS;
        int c0 = q * 8;
        #pragma unroll
        for (int l = 0; l < NL; l++) {
            const float4* bp = (const float4*)(BC + l*SZ_BC + r*BCS + c0);
            float4 v0 = bp[0], v1 = bp[1], v2 = bp[2], v3 = bp[3];
            float bb[15] = {v0.x,v0.y,v0.z,v0.w, v1.x,v1.y,v1.z,v1.w,
                            v2.x,v2.y,v2.z,v2.w, v3.x,v3.y,v3.z};
            float w[15];
            #pragma unroll
            for (int d = 0; d < 15; d++) w[d] = bb[d]*bb[d];
            prefix_store(w, R + l*SZ_HB + r*HS + c0);
        }
    }
    __syncthreads();

    float rsjjR[NL][4];
    #pragma unroll
    for (int l = 0; l < NL; l++) {
        float v4[4];
        vsum4(R + l*SZ_HB, g, cl, v4);
        #pragma unroll
        for (int k = 0; k < 4; k++) rsjjR[l][k] = rsqrtf(fmaxf(v4[k], EPS));
    }
    // o-loop head barrier orders these R reads before hmean overwrites R

    // ---------------- phase 2: outputs ----------------
    for (int o = 0; o < NO; o++) {
        const float* src = outs + (size_t)(b*NO + o)*NPIX;
        if (interior) load_tile<true>(src, X, tx0, ty0, tid);
        else          load_tile<false>(src, X, tx0, ty0, tid);
        __syncthreads();                  // (1) X visible; retires prior R/vsum readers
        hmean(X, Hm, tid);
        __syncthreads();                  // (2)
        if (interior) centered<true>(X, Hm, AC, tx0, ty0, tid);
        else          centered<false>(X, Hm, AC, tx0, ty0, tid);
        __syncthreads();                  // (3) AC ready; Hm dead -> R hosts H0..H4

        // fused hprod: ac window loaded once; j=0 -> ac*ac, j=1..4 -> ac*bc_{j-1}
        for (int idx = tid; idx < TS*8; idx += NT) {
            int r = idx % TS, q = idx / TS;
            int c0 = q * 8;
            const float4* ap = (const float4*)(AC + r*BCS + c0);
            float4 a0 = ap[0], a1 = ap[1], a2 = ap[2], a3 = ap[3];
            float a[15] = {a0.x,a0.y,a0.z,a0.w, a1.x,a1.y,a1.z,a1.w,
                           a2.x,a2.y,a2.z,a2.w, a3.x,a3.y,a3.z};
            {
                float w[15];
                #pragma unroll
                for (int d = 0; d < 15; d++) w[d] = a[d]*a[d];
                prefix_store(w, R + r*HS + c0);
            }
            #pragma unroll
            for (int l = 0; l < NL; l++) {
                const float4* bp = (const float4*)(BC + l*SZ_BC + r*BCS + c0);
                float4 u0 = bp[0], u1 = bp[1], u2 = bp[2], u3 = bp[3];
                float bb[15] = {u0.x,u0.y,u0.z,u0.w, u1.x,u1.y,u1.z,u1.w,
                                u2.x,u2.y,u2.z,u2.w, u3.x,u3.y,u3.z};
                float w[15];
                #pragma unroll
                for (int d = 0; d < 15; d++) w[d] = a[d]*bb[d];
                prefix_store(w, R + (l+1)*SZ_HB + r*HS + c0);
            }
        }
        __syncthreads();                  // (4) H0..H4 ready

        float rsii[4];
        {
            float v4[4];
            vsum4(R, g, cl, v4);
            #pragma unroll
            for (int k = 0; k < 4; k++) rsii[k] = rsqrtf(fmaxf(v4[k], EPS));
        }

        float maxcc[4];
        #pragma unroll
        for (int k = 0; k < 4; k++) maxcc[k] = -1.0f;

        #pragma unroll
        for (int l = 0; l < NL; l++) {
            float sij4[4];
            vsum4(R + (l+1)*SZ_HB, g, cl, sij4);
            #pragma unroll
            for (int k = 0; k < 4; k++) {
                float cc = sij4[k] * (rsii[k] * rsjjR[l][k]);
                maxcc[k] = fmaxf(maxcc[k], cc);
            }
        }

        float local = 0.f;
        #pragma unroll
        for (int k = 0; k < 4; k++) local += 1.0f - fminf(1.0f, maxcc[k]);
        #pragma unroll
        for (int off = 16; off > 0; off >>= 1)
            local += __shfl_down_sync(0xFFFFFFFFu, local, off);
        if (lane == 0) s_red[o*32 + wid] = local;   // deferred: no tail barrier
        // next loop-head barrier (1) orders the R reads above before hmean rewrites R
    }

    // ---------------- deferred per-output reduction ----------------
    __syncthreads();
    if (wid < NO) {
        float v = s_red[wid*32 + lane];
        #pragma unroll
        for (int off = 16; off > 0; off >>= 1)
            v += __shfl_down_sync(0xFFFFFFFFu, v, off);
        if (lane == 0)
            d_partial[(b*NO + wid)*64 + blockIdx.y*8 + blockIdx.x] = v;
    }
    __syncthreads();

    // ---------------- in-kernel finalize (last CTA, fixed-order sums) ------
    if (tid == 0) {
        __threadfence();
        unsigned int v = atomicAdd(&d_count, 1u);
        s_flag = (v == NCTA - 1) ? 1u : 0u;
    }
    __syncthreads();
    if (s_flag) {
        __threadfence();   // acquire: all CTAs' d_partial visible
        if (tid < NB*NO) {
            float s = 0.f;
            for (int i = 0; i < 64; i++) s += d_partial[tid*64 + i];
            float m = s * (1.0f / (float)NPIX);
            s_vals[tid] = m;
            if (1 + tid < out_size) out[1 + tid] = m;
        }
        __syncthreads();
        if (tid == 0) {
            float s = 0.f;
            #pragma unroll
            for (int i = 0; i < NB*NO; i++) s += s_vals[i];
            if (out_size > 0) out[0] = s / (float)(NB*NO);
            d_count = 0;   // reset for next graph replay
        }
    }
}

extern "C" void kernel_launch(void* const* d_in, const int* in_sizes, int n_in,
                              void* d_out, int out_size) {
    const float* outs = (const float*)d_in[0];
    const float* labs = (const float*)d_in[1];
    if (n_in >= 2 && in_sizes[0] < in_sizes[1]) {  // defensive: outputs is larger
        const float* tmp = outs; outs = labs; labs = tmp;
    }

    const int SMEM = SMEM_FLOATS * (int)sizeof(float);   // 230,688 B
    cudaFuncSetAttribute(fused_kernel, cudaFuncAttributeMaxDynamicSharedMemorySize, SMEM);
    fused_kernel<<<dim3(8, 8, NB), NT, SMEM>>>(outs, labs, (float*)d_out, out_size);
}

// round 14
// speedup vs baseline: 1.2803x; 1.1673x over previous
#include <cuda_runtime.h>
#include <math.h>

#define IMG   512
#define NPIX  (IMG*IMG)
#define NB    4
#define NO    6
#define NL    4
#define TILE  64
#define TS    71      // centered extent (rows & cols)
#define BCS   76      // BC/AC stride: conflict-free float4 rows
#define XR    78      // raw tile rows
#define XS2   84      // raw tile stride; cols 0..79 written (X col = raw offset + 2)
#define HMS   76      // Hm stride
#define HS    68      // H box-buffer stride: cf float4, 16B aligned
#define EPS   1e-20f
#define NT    1024
#define NCTA  (8*8*NB)   // 256

// sizes in floats (all multiples of 4)
#define SZ_BC   (TS*BCS)       // 5396
#define SZ_X    (XR*XS2)       // 6552
#define SZ_HM   (XR*HMS)       // 5928
#define SZ_HB   (TS*HS)        // 4828
#define R_FLOATS (5*SZ_HB)     // 24140 (hosts Hm transiently; Hm dead before H written)
#define SMEM_FLOATS (NL*SZ_BC + SZ_BC + R_FLOATS + SZ_X)   // 57672 -> 230,688 B

__device__ float d_partial[NB*NO*64];
__device__ unsigned int d_count = 0;

// ---- cp.async helpers (16B granules) ----
__device__ __forceinline__ void cp_async16(float* dst_smem, const float* src) {
    unsigned int d = (unsigned int)__cvta_generic_to_shared(dst_smem);
    asm volatile("cp.async.cg.shared.global [%0], [%1], 16;" :: "r"(d), "l"(src));
}
#define CP_COMMIT() asm volatile("cp.async.commit_group;" ::: "memory")
#define CP_WAIT0()  asm volatile("cp.async.wait_group 0;" ::: "memory")

// ---- async tile prefetch: X[r][4j..4j+3] = raw[ty0+r-6][tx0-8+4j ..+3] ----
// 16B-aligned both sides; out-of-image granules skipped (pre-zeroed once).
template<bool IN>
__device__ __forceinline__ void prefetch_tile(const float* __restrict__ src, float* __restrict__ X,
                                              int tx0, int ty0, int wid, int lane) {
    if (lane < 20) {
        #pragma unroll
        for (int i = 0; i < 3; i++) {
            int r = wid + 32*i;
            if (i < 2 || r < XR) {
                int gr = ty0 + r - 6;
                int gc0 = tx0 - 8 + 4*lane;
                if (IN || ((unsigned)gr < (unsigned)IMG && (unsigned)gc0 < (unsigned)IMG))
                    cp_async16(X + r*XS2 + 4*lane, src + gr*IMG + gc0);
            }
        }
    }
    CP_COMMIT();
}

// ---- one-time zeroing of out-of-image granules (non-interior tiles) ----
__device__ __forceinline__ void zero_pad(float* __restrict__ X, int tx0, int ty0, int wid, int lane) {
    if (lane < 20) {
        #pragma unroll
        for (int i = 0; i < 3; i++) {
            int r = wid + 32*i;
            if (i < 2 || r < XR) {
                int gr = ty0 + r - 6;
                int gc0 = tx0 - 8 + 4*lane;
                if (!((unsigned)gr < (unsigned)IMG && (unsigned)gc0 < (unsigned)IMG))
                    *(float4*)(X + r*XS2 + 4*lane) = make_float4(0.f,0.f,0.f,0.f);
            }
        }
    }
}

// ---- Hm[r][c] = sum_{d=0..7} raw[r][c-6+d]; raw offset v -> X col v+2 ----
__device__ __forceinline__ void hmean(const float* __restrict__ X, float* __restrict__ Hm, int tid) {
    for (int idx = tid; idx < XR*9; idx += NT) {
        int r = idx % XR, q = idx / XR;
        int c0 = q * 8;                                   // 0..64
        const float4* xp = (const float4*)(X + r*XS2 + c0);
        float4 v0 = xp[0], v1 = xp[1], v2 = xp[2], v3 = xp[3], v4 = xp[4];
        float t[20] = {v0.x,v0.y,v0.z,v0.w, v1.x,v1.y,v1.z,v1.w,
                       v2.x,v2.y,v2.z,v2.w, v3.x,v3.y,v3.z,v3.w,
                       v4.x,v4.y,v4.z,v4.w};
        // window for output k: t[k+2 .. k+9]
        float o[8];
        float s = t[2]+t[3]+t[4]+t[5]+t[6]+t[7]+t[8]+t[9];
        o[0] = s;
        #pragma unroll
        for (int k = 1; k < 8; k++) { s += t[k+9] - t[k+1]; o[k] = s; }
        float4* hp = (float4*)(Hm + r*HMS + c0);
        hp[0] = make_float4(o[0],o[1],o[2],o[3]);
        hp[1] = make_float4(o[4],o[5],o[6],o[7]);
    }
}

// ---- OUT[r][c] = inside ? raw(ty0+r-3, tx0+c-3) - boxmean : 0, r,c<71 ----
template<bool IN>
__device__ __forceinline__ void centered(const float* __restrict__ X, const float* __restrict__ Hm,
                                         float* __restrict__ OUT, int tx0, int ty0, int tid) {
    for (int idx = tid; idx < TS*9; idx += NT) {
        int c = idx % TS, q = idx / TS;
        int r0 = q * 8;
        int cnt = min(8, TS - r0);
        float h[15];
        #pragma unroll
        for (int d = 0; d < 15; d++) h[d] = Hm[min(r0 + d, XR-1)*HMS + c];
        float xv[8];
        #pragma unroll
        for (int k = 0; k < 8; k++) xv[k] = X[(r0 + k + 3)*XS2 + (c + 5)];  // +2 shift
        float s = h[0]+h[1]+h[2]+h[3]+h[4]+h[5]+h[6]+h[7];
        bool cin = IN || ((unsigned)(tx0 + c - 3) < (unsigned)IMG);
        #pragma unroll
        for (int k = 0; k < 8; k++) {
            if (k < cnt) {
                int r = r0 + k;
                float v;
                if (IN) {
                    v = xv[k] - s * (1.f/64.f);
                } else {
                    int gr = ty0 + r - 3;
                    v = 0.f;
                    if (cin && (unsigned)gr < (unsigned)IMG) v = xv[k] - s * (1.f/64.f);
                }
                OUT[r*BCS + c] = v;
                if (k + 1 < cnt) s += h[k+8] - h[k];
            }
        }
    }
}

// ---- running window-sum of w[0..14] -> 8 outputs, float4-stored ----
__device__ __forceinline__ void prefix_store(const float* w, float* __restrict__ hr) {
    float o[8];
    float s = w[0]+w[1]+w[2]+w[3]+w[4]+w[5]+w[6]+w[7];
    o[0] = s;
    #pragma unroll
    for (int k = 1; k < 8; k++) { s += w[k+7] - w[k-1]; o[k] = s; }
    float4* hp = (float4*)hr;
    hp[0] = make_float4(o[0],o[1],o[2],o[3]);
    hp[1] = make_float4(o[4],o[5],o[6],o[7]);
}

// ---- 4 vertical window sums of Hb at column cl, row group g ----
__device__ __forceinline__ void vsum4(const float* __restrict__ Hb, int g, int cl, float* out) {
    float ps[12];
    ps[0] = 0.f;
    #pragma unroll
    for (int k = 0; k < 11; k++) ps[k+1] = ps[k] + Hb[(g*4 + k)*HS + cl];
    #pragma unroll
    for (int k = 0; k < 4; k++) out[k] = ps[k+8] - ps[k];
}

// =========================================================================
// fused: one CTA per (batch, 64x64 tile), 1024 threads, finalize in-kernel.
// =========================================================================
__global__ void __launch_bounds__(NT, 1)
fused_kernel(const float* __restrict__ outs, const float* __restrict__ labs,
             float* __restrict__ out, int out_size) {
    extern __shared__ float sm[];
    float* BC = sm;                  // NL * 5396
    float* AC = BC + NL*SZ_BC;       // 5396
    float* R  = AC + SZ_BC;          // 24140: Hm (transient) / H0..H4
    float* Hm = R;                   // 5928 (dead before H written)
    float* X  = R + R_FLOATS;        // 6552 DEDICATED raw-tile buffer
    __shared__ float s_red[NO*32];
    __shared__ unsigned int s_flag;
    __shared__ float s_vals[NB*NO];

    int tx0 = blockIdx.x * TILE, ty0 = blockIdx.y * TILE;
    int b = blockIdx.z;
    int tid = threadIdx.x;
    int cl = tid & 63, g = tid >> 6;      // pixel column / row-group (g 0..15, 4 rows)
    int lane = tid & 31, wid = tid >> 5;
    const bool interior = (blockIdx.x >= 1 && blockIdx.x <= 6 &&
                           blockIdx.y >= 1 && blockIdx.y <= 6);

    if (!interior) zero_pad(X, tx0, ty0, wid, lane);   // padding persists

    // ---------------- phase 1: labels -> BC[l] ----------------
    for (int l = 0; l < NL; l++) {
        const float* src = labs + (size_t)(b*NL + l)*NPIX;
        if (interior) prefetch_tile<true>(src, X, tx0, ty0, wid, lane);
        else          prefetch_tile<false>(src, X, tx0, ty0, wid, lane);
        CP_WAIT0();
        __syncthreads();
        hmean(X, Hm, tid);
        __syncthreads();
        if (interior) centered<true>(X, Hm, BC + l*SZ_BC, tx0, ty0, tid);
        else          centered<false>(X, Hm, BC + l*SZ_BC, tx0, ty0, tid);
        __syncthreads();                  // BC[l] ready; X/Hm readers retired
    }

    // prefetch output 0 now -> overlaps the whole sjj phase (X not read below)
    {
        const float* src = outs + (size_t)(b*NO)*NPIX;
        if (interior) prefetch_tile<true>(src, X, tx0, ty0, wid, lane);
        else          prefetch_tile<false>(src, X, tx0, ty0, wid, lane);
    }

    // fused sjj phase: box-row sums of bc_l^2 for all 4 labels -> H0..H3 (568 items)
    for (int idx = tid; idx < TS*8; idx += NT) {
        int r = idx % TS, q = idx / TS;
        int c0 = q * 8;
        #pragma unroll
        for (int l = 0; l < NL; l++) {
            const float4* bp = (const float4*)(BC + l*SZ_BC + r*BCS + c0);
            float4 v0 = bp[0], v1 = bp[1], v2 = bp[2], v3 = bp[3];
            float bb[15] = {v0.x,v0.y,v0.z,v0.w, v1.x,v1.y,v1.z,v1.w,
                            v2.x,v2.y,v2.z,v2.w, v3.x,v3.y,v3.z};
            float w[15];
            #pragma unroll
            for (int d = 0; d < 15; d++) w[d] = bb[d]*bb[d];
            prefix_store(w, R + l*SZ_HB + r*HS + c0);
        }
    }
    __syncthreads();

    float rsjjR[NL][4];
    #pragma unroll
    for (int l = 0; l < NL; l++) {
        float v4[4];
        vsum4(R + l*SZ_HB, g, cl, v4);
        #pragma unroll
        for (int k = 0; k < 4; k++) rsjjR[l][k] = rsqrtf(fmaxf(v4[k], EPS));
    }
    // o-loop head barrier orders these R reads before hmean overwrites R

    // ---------------- phase 2: outputs ----------------
    for (int o = 0; o < NO; o++) {
        CP_WAIT0();
        __syncthreads();                  // (1) X(o) visible; retires prior R/vsum readers
        hmean(X, Hm, tid);
        __syncthreads();                  // (2)
        if (interior) centered<true>(X, Hm, AC, tx0, ty0, tid);
        else          centered<false>(X, Hm, AC, tx0, ty0, tid);
        __syncthreads();                  // (3) AC ready; X free -> prefetch o+1
        if (o < NO-1) {
            const float* src = outs + (size_t)(b*NO + o + 1)*NPIX;
            if (interior) prefetch_tile<true>(src, X, tx0, ty0, wid, lane);
            else          prefetch_tile<false>(src, X, tx0, ty0, wid, lane);
        }

        // fused hprod: ac window loaded once; j=0 -> ac*ac, j=1..4 -> ac*bc_{j-1}
        for (int idx = tid; idx < TS*8; idx += NT) {
            int r = idx % TS, q = idx / TS;
            int c0 = q * 8;
            const float4* ap = (const float4*)(AC + r*BCS + c0);
            float4 a0 = ap[0], a1 = ap[1], a2 = ap[2], a3 = ap[3];
            float a[15] = {a0.x,a0.y,a0.z,a0.w, a1.x,a1.y,a1.z,a1.w,
                           a2.x,a2.y,a2.z,a2.w, a3.x,a3.y,a3.z};
            {
                float w[15];
                #pragma unroll
                for (int d = 0; d < 15; d++) w[d] = a[d]*a[d];
                prefix_store(w, R + r*HS + c0);
            }
            #pragma unroll
            for (int l = 0; l < NL; l++) {
                const float4* bp = (const float4*)(BC + l*SZ_BC + r*BCS + c0);
                float4 u0 = bp[0], u1 = bp[1], u2 = bp[2], u3 = bp[3];
                float bb[15] = {u0.x,u0.y,u0.z,u0.w, u1.x,u1.y,u1.z,u1.w,
                                u2.x,u2.y,u2.z,u2.w, u3.x,u3.y,u3.z};
                float w[15];
                #pragma unroll
                for (int d = 0; d < 15; d++) w[d] = a[d]*bb[d];
                prefix_store(w, R + (l+1)*SZ_HB + r*HS + c0);
            }
        }
        __syncthreads();                  // (4) H0..H4 ready

        float rsii[4];
        {
            float v4[4];
            vsum4(R, g, cl, v4);
            #pragma unroll
            for (int k = 0; k < 4; k++) rsii[k] = rsqrtf(fmaxf(v4[k], EPS));
        }

        float maxcc[4];
        #pragma unroll
        for (int k = 0; k < 4; k++) maxcc[k] = -1.0f;

        #pragma unroll
        for (int l = 0; l < NL; l++) {
            float sij4[4];
            vsum4(R + (l+1)*SZ_HB, g, cl, sij4);
            #pragma unroll
            for (int k = 0; k < 4; k++) {
                float cc = sij4[k] * (rsii[k] * rsjjR[l][k]);
                maxcc[k] = fmaxf(maxcc[k], cc);
            }
        }

        float local = 0.f;
        #pragma unroll
        for (int k = 0; k < 4; k++) local += 1.0f - fminf(1.0f, maxcc[k]);
        #pragma unroll
        for (int off = 16; off > 0; off >>= 1)
            local += __shfl_down_sync(0xFFFFFFFFu, local, off);
        if (lane == 0) s_red[o*32 + wid] = local;   // deferred: no tail barrier
        // next loop-head barrier (1) orders the R reads above before hmean rewrites R
    }

    // ---------------- deferred per-output reduction ----------------
    __syncthreads();
    if (wid < NO) {
        float v = s_red[wid*32 + lane];
        #pragma unroll
        for (int off = 16; off > 0; off >>= 1)
            v += __shfl_down_sync(0xFFFFFFFFu, v, off);
        if (lane == 0)
            d_partial[(b*NO + wid)*64 + blockIdx.y*8 + blockIdx.x] = v;
    }
    __syncthreads();

    // ---------------- in-kernel finalize (last CTA, fixed-order sums) ------
    if (tid == 0) {
        __threadfence();
        unsigned int v = atomicAdd(&d_count, 1u);
        s_flag = (v == NCTA - 1) ? 1u : 0u;
    }
    __syncthreads();
    if (s_flag) {
        __threadfence();   // acquire: all CTAs' d_partial visible
        if (tid < NB*NO) {
            float s = 0.f;
            for (int i = 0; i < 64; i++) s += d_partial[tid*64 + i];
            float m = s * (1.0f / (float)NPIX);
            s_vals[tid] = m;
            if (1 + tid < out_size) out[1 + tid] = m;
        }
        __syncthreads();
        if (tid == 0) {
            float s = 0.f;
            #pragma unroll
            for (int i = 0; i < NB*NO; i++) s += s_vals[i];
            if (out_size > 0) out[0] = s / (float)(NB*NO);
            d_count = 0;   // reset for next graph replay
        }
    }
}

extern "C" void kernel_launch(void* const* d_in, const int* in_sizes, int n_in,
                              void* d_out, int out_size) {
    const float* outs = (const float*)d_in[0];
    const float* labs = (const float*)d_in[1];
    if (n_in >= 2 && in_sizes[0] < in_sizes[1]) {  // defensive: outputs is larger
        const float* tmp = outs; outs = labs; labs = tmp;
    }

    const int SMEM = SMEM_FLOATS * (int)sizeof(float);   // 230,688 B
    cudaFuncSetAttribute(fused_kernel, cudaFuncAttributeMaxDynamicSharedMemorySize, SMEM);
    fused_kernel<<<dim3(8, 8, NB), NT, SMEM>>>(outs, labs, (float*)d_out, out_size);
}

// round 15
// speedup vs baseline: 1.3166x; 1.0284x over previous
#include <cuda_runtime.h>
#include <math.h>

#define IMG   512
#define NPIX  (IMG*IMG)
#define NB    4
#define NO    6
#define NL    4
#define TILE  64
#define TS    71      // centered extent (rows & cols)
#define BCS   76      // BC/AC stride: conflict-free float4 rows
#define XR    78      // raw tile rows
#define XS2   84      // raw tile stride; cols 0..79 written (X col = raw offset + 2)
#define HMS   76      // Hm stride
#define HS    68      // H box-buffer stride: cf float4, 16B aligned
#define EPS   1e-20f
#define NT    1024
#define NCTA  (8*8*NB)   // 256

// sizes in floats (all multiples of 4)
#define SZ_BC   (TS*BCS)       // 5396
#define SZ_X    (XR*XS2)       // 6552
#define SZ_HM   (XR*HMS)       // 5928
#define SZ_HB   (TS*HS)        // 4828
#define R_FLOATS (5*SZ_HB)     // 24140 (hosts Hm + label-phase X1 transiently)
#define SMEM_FLOATS (NL*SZ_BC + SZ_BC + R_FLOATS + SZ_X)   // 57672 -> 230,688 B

__device__ float d_partial[NB*NO*64];
__device__ unsigned int d_count = 0;

// ---- cp.async helpers (16B granules) ----
__device__ __forceinline__ void cp_async16(float* dst_smem, const float* src) {
    unsigned int d = (unsigned int)__cvta_generic_to_shared(dst_smem);
    asm volatile("cp.async.cg.shared.global [%0], [%1], 16;" :: "r"(d), "l"(src));
}
#define CP_COMMIT() asm volatile("cp.async.commit_group;" ::: "memory")
#define CP_WAIT0()  asm volatile("cp.async.wait_group 0;" ::: "memory")

// ---- async tile prefetch: X[r][4j..4j+3] = raw[ty0+r-6][tx0-8+4j ..+3] ----
template<bool IN>
__device__ __forceinline__ void prefetch_tile(const float* __restrict__ src, float* __restrict__ X,
                                              int tx0, int ty0, int wid, int lane) {
    if (lane < 20) {
        #pragma unroll
        for (int i = 0; i < 3; i++) {
            int r = wid + 32*i;
            if (i < 2 || r < XR) {
                int gr = ty0 + r - 6;
                int gc0 = tx0 - 8 + 4*lane;
                if (IN || ((unsigned)gr < (unsigned)IMG && (unsigned)gc0 < (unsigned)IMG))
                    cp_async16(X + r*XS2 + 4*lane, src + gr*IMG + gc0);
            }
        }
    }
    CP_COMMIT();
}

// ---- one-time zeroing of out-of-image granules (non-interior tiles) ----
__device__ __forceinline__ void zero_pad(float* __restrict__ X, int tx0, int ty0, int wid, int lane) {
    if (lane < 20) {
        #pragma unroll
        for (int i = 0; i < 3; i++) {
            int r = wid + 32*i;
            if (i < 2 || r < XR) {
                int gr = ty0 + r - 6;
                int gc0 = tx0 - 8 + 4*lane;
                if (!((unsigned)gr < (unsigned)IMG && (unsigned)gc0 < (unsigned)IMG))
                    *(float4*)(X + r*XS2 + 4*lane) = make_float4(0.f,0.f,0.f,0.f);
            }
        }
    }
}

// ---- Hm[r][c] = sum_{d=0..7} raw[r][c-6+d]; raw offset v -> X col v+2 ----
__device__ __forceinline__ void hmean(const float* __restrict__ X, float* __restrict__ Hm, int tid) {
    for (int idx = tid; idx < XR*9; idx += NT) {
        int r = idx % XR, q = idx / XR;
        int c0 = q * 8;                                   // 0..64
        const float4* xp = (const float4*)(X + r*XS2 + c0);
        float4 v0 = xp[0], v1 = xp[1], v2 = xp[2], v3 = xp[3], v4 = xp[4];
        float t[20] = {v0.x,v0.y,v0.z,v0.w, v1.x,v1.y,v1.z,v1.w,
                       v2.x,v2.y,v2.z,v2.w, v3.x,v3.y,v3.z,v3.w,
                       v4.x,v4.y,v4.z,v4.w};
        float o[8];
        float s = t[2]+t[3]+t[4]+t[5]+t[6]+t[7]+t[8]+t[9];
        o[0] = s;
        #pragma unroll
        for (int k = 1; k < 8; k++) { s += t[k+9] - t[k+1]; o[k] = s; }
        float4* hp = (float4*)(Hm + r*HMS + c0);
        hp[0] = make_float4(o[0],o[1],o[2],o[3]);
        hp[1] = make_float4(o[4],o[5],o[6],o[7]);
    }
}

// ---- OUT[r][c] = inside ? raw(ty0+r-3, tx0+c-3) - boxmean : 0, r,c<71 ----
template<bool IN>
__device__ __forceinline__ void centered(const float* __restrict__ X, const float* __restrict__ Hm,
                                         float* __restrict__ OUT, int tx0, int ty0, int tid) {
    for (int idx = tid; idx < TS*9; idx += NT) {
        int c = idx % TS, q = idx / TS;
        int r0 = q * 8;
        int cnt = min(8, TS - r0);
        float h[15];
        #pragma unroll
        for (int d = 0; d < 15; d++) h[d] = Hm[min(r0 + d, XR-1)*HMS + c];
        float xv[8];
        #pragma unroll
        for (int k = 0; k < 8; k++) xv[k] = X[(r0 + k + 3)*XS2 + (c + 5)];  // +2 shift
        float s = h[0]+h[1]+h[2]+h[3]+h[4]+h[5]+h[6]+h[7];
        bool cin = IN || ((unsigned)(tx0 + c - 3) < (unsigned)IMG);
        #pragma unroll
        for (int k = 0; k < 8; k++) {
            if (k < cnt) {
                int r = r0 + k;
                float v;
                if (IN) {
                    v = xv[k] - s * (1.f/64.f);
                } else {
                    int gr = ty0 + r - 3;
                    v = 0.f;
                    if (cin && (unsigned)gr < (unsigned)IMG) v = xv[k] - s * (1.f/64.f);
                }
                OUT[r*BCS + c] = v;
                if (k + 1 < cnt) s += h[k+8] - h[k];
            }
        }
    }
}

// ---- running window-sum of w[0..14] -> 8 outputs, float4-stored ----
__device__ __forceinline__ void prefix_store(const float* w, float* __restrict__ hr) {
    float o[8];
    float s = w[0]+w[1]+w[2]+w[3]+w[4]+w[5]+w[6]+w[7];
    o[0] = s;
    #pragma unroll
    for (int k = 1; k < 8; k++) { s += w[k+7] - w[k-1]; o[k] = s; }
    float4* hp = (float4*)hr;
    hp[0] = make_float4(o[0],o[1],o[2],o[3]);
    hp[1] = make_float4(o[4],o[5],o[6],o[7]);
}

// ---- 4 vertical window sums of Hb at column cl, row group g ----
__device__ __forceinline__ void vsum4(const float* __restrict__ Hb, int g, int cl, float* out) {
    float ps[12];
    ps[0] = 0.f;
    #pragma unroll
    for (int k = 0; k < 11; k++) ps[k+1] = ps[k] + Hb[(g*4 + k)*HS + cl];
    #pragma unroll
    for (int k = 0; k < 4; k++) out[k] = ps[k+8] - ps[k];
}

// =========================================================================
// fused: one CTA per (batch, 64x64 tile), 1024 threads, finalize in-kernel.
// =========================================================================
__global__ void __launch_bounds__(NT, 1)
fused_kernel(const float* __restrict__ outs, const float* __restrict__ labs,
             float* __restrict__ out, int out_size) {
    extern __shared__ float sm[];
    float* BC = sm;                  // NL * 5396
    float* AC = BC + NL*SZ_BC;       // 5396
    float* R  = AC + SZ_BC;          // 24140: Hm + X1 (label phase) / H0..H4 (o phase)
    float* Hm = R;                   // 5928 (dead before H written)
    float* X1 = R + SZ_HM;           // 6552 label-phase second buffer (dead before sjj)
    float* X  = R + R_FLOATS;        // 6552 DEDICATED buffer
    __shared__ float s_red[NO*32];
    __shared__ unsigned int s_flag;
    __shared__ float s_vals[NB*NO];

    int tx0 = blockIdx.x * TILE, ty0 = blockIdx.y * TILE;
    int b = blockIdx.z;
    int tid = threadIdx.x;
    int cl = tid & 63, g = tid >> 6;      // pixel column / row-group (g 0..15, 4 rows)
    int lane = tid & 31, wid = tid >> 5;
    const bool interior = (blockIdx.x >= 1 && blockIdx.x <= 6 &&
                           blockIdx.y >= 1 && blockIdx.y <= 6);

    if (!interior) {                      // padding persists per buffer
        zero_pad(X,  tx0, ty0, wid, lane);
        zero_pad(X1, tx0, ty0, wid, lane);
    }
    // kick off label 0 into X
    if (interior) prefetch_tile<true >(labs + (size_t)(b*NL)*NPIX, X, tx0, ty0, wid, lane);
    else          prefetch_tile<false>(labs + (size_t)(b*NL)*NPIX, X, tx0, ty0, wid, lane);

    // ---------------- phase 1: labels -> BC[l], X double-buffered ----------
    // l even: consume X, prefetch next into X1; l odd: vice versa.
    // Prefetch target's readers always retired >=1 barrier earlier (audited).
    for (int l = 0; l < NL; l++) {
        float* Xc = (l & 1) ? X1 : X;
        float* Xn = (l & 1) ? X  : X1;
        CP_WAIT0();
        __syncthreads();                  // Xc visible to all threads
        const float* nxt = (l < NL-1) ? labs + (size_t)(b*NL + l + 1)*NPIX
                                      : outs + (size_t)(b*NO)*NPIX;
        float* ndst = (l < NL-1) ? Xn : X;   // out0 -> dedicated X (readers retired l=2)
        if (interior) prefetch_tile<true >(nxt, ndst, tx0, ty0, wid, lane);
        else          prefetch_tile<false>(nxt, ndst, tx0, ty0, wid, lane);
        hmean(Xc, Hm, tid);
        __syncthreads();
        if (interior) centered<true >(Xc, Hm, BC + l*SZ_BC, tx0, ty0, tid);
        else          centered<false>(Xc, Hm, BC + l*SZ_BC, tx0, ty0, tid);
        __syncthreads();                  // BC[l] ready; Xc/Hm readers retired
    }
    // out0 load (into X) now overlaps the whole sjj phase; X1/Hm dead -> R free

    // fused sjj phase: box-row sums of bc_l^2 for all 4 labels -> H0..H3 (568 items)
    for (int idx = tid; idx < TS*8; idx += NT) {
        int r = idx % TS, q = idx / TS;
        int c0 = q * 8;
        #pragma unroll
        for (int l = 0; l < NL; l++) {
            const float4* bp = (const float4*)(BC + l*SZ_BC + r*BCS + c0);
            float4 v0 = bp[0], v1 = bp[1], v2 = bp[2], v3 = bp[3];
            float bb[15] = {v0.x,v0.y,v0.z,v0.w, v1.x,v1.y,v1.z,v1.w,
                            v2.x,v2.y,v2.z,v2.w, v3.x,v3.y,v3.z};
            float w[15];
            #pragma unroll
            for (int d = 0; d < 15; d++) w[d] = bb[d]*bb[d];
            prefix_store(w, R + l*SZ_HB + r*HS + c0);
        }
    }
    __syncthreads();

    float rsjjR[NL][4];
    #pragma unroll
    for (int l = 0; l < NL; l++) {
        float v4[4];
        vsum4(R + l*SZ_HB, g, cl, v4);
        #pragma unroll
        for (int k = 0; k < 4; k++) rsjjR[l][k] = rsqrtf(fmaxf(v4[k], EPS));
    }
    // o-loop head barrier orders these R reads before hmean overwrites R

    // ---------------- phase 2: outputs ----------------
    for (int o = 0; o < NO; o++) {
        CP_WAIT0();
        __syncthreads();                  // (1) X(o) visible; retires prior R/vsum readers
        hmean(X, Hm, tid);
        __syncthreads();                  // (2)
        if (interior) centered<true >(X, Hm, AC, tx0, ty0, tid);
        else          centered<false>(X, Hm, AC, tx0, ty0, tid);
        __syncthreads();                  // (3) AC ready; X free -> prefetch o+1
        if (o < NO-1) {
            const float* src = outs + (size_t)(b*NO + o + 1)*NPIX;
            if (interior) prefetch_tile<true >(src, X, tx0, ty0, wid, lane);
            else          prefetch_tile<false>(src, X, tx0, ty0, wid, lane);
        }

        // fused hprod: ac window loaded once; j=0 -> ac*ac, j=1..4 -> ac*bc_{j-1}
        for (int idx = tid; idx < TS*8; idx += NT) {
            int r = idx % TS, q = idx / TS;
            int c0 = q * 8;
            const float4* ap = (const float4*)(AC + r*BCS + c0);
            float4 a0 = ap[0], a1 = ap[1], a2 = ap[2], a3 = ap[3];
            float a[15] = {a0.x,a0.y,a0.z,a0.w, a1.x,a1.y,a1.z,a1.w,
                           a2.x,a2.y,a2.z,a2.w, a3.x,a3.y,a3.z};
            {
                float w[15];
                #pragma unroll
                for (int d = 0; d < 15; d++) w[d] = a[d]*a[d];
                prefix_store(w, R + r*HS + c0);
            }
            #pragma unroll
            for (int l = 0; l < NL; l++) {
                const float4* bp = (const float4*)(BC + l*SZ_BC + r*BCS + c0);
                float4 u0 = bp[0], u1 = bp[1], u2 = bp[2], u3 = bp[3];
                float bb[15] = {u0.x,u0.y,u0.z,u0.w, u1.x,u1.y,u1.z,u1.w,
                                u2.x,u2.y,u2.z,u2.w, u3.x,u3.y,u3.z};
                float w[15];
                #pragma unroll
                for (int d = 0; d < 15; d++) w[d] = a[d]*bb[d];
                prefix_store(w, R + (l+1)*SZ_HB + r*HS + c0);
            }
        }
        __syncthreads();                  // (4) H0..H4 ready

        float rsii[4];
        {
            float v4[4];
            vsum4(R, g, cl, v4);
            #pragma unroll
            for (int k = 0; k < 4; k++) rsii[k] = rsqrtf(fmaxf(v4[k], EPS));
        }

        float maxcc[4];
        #pragma unroll
        for (int k = 0; k < 4; k++) maxcc[k] = -1.0f;

        #pragma unroll
        for (int l = 0; l < NL; l++) {
            float sij4[4];
            vsum4(R + (l+1)*SZ_HB, g, cl, sij4);
            #pragma unroll
            for (int k = 0; k < 4; k++) {
                float cc = sij4[k] * (rsii[k] * rsjjR[l][k]);
                maxcc[k] = fmaxf(maxcc[k], cc);
            }
        }

        float local = 0.f;
        #pragma unroll
        for (int k = 0; k < 4; k++) local += 1.0f - fminf(1.0f, maxcc[k]);
        #pragma unroll
        for (int off = 16; off > 0; off >>= 1)
            local += __shfl_down_sync(0xFFFFFFFFu, local, off);
        if (lane == 0) s_red[o*32 + wid] = local;   // deferred: no tail barrier
        // next loop-head barrier (1) orders the R reads above before hmean rewrites R
    }

    // ---------------- deferred per-output reduction ----------------
    __syncthreads();
    if (wid < NO) {
        float v = s_red[wid*32 + lane];
        #pragma unroll
        for (int off = 16; off > 0; off >>= 1)
            v += __shfl_down_sync(0xFFFFFFFFu, v, off);
        if (lane == 0)
            d_partial[(b*NO + wid)*64 + blockIdx.y*8 + blockIdx.x] = v;
    }
    __syncthreads();

    // ---------------- in-kernel finalize (last CTA, fixed-order sums) ------
    if (tid == 0) {
        __threadfence();
        unsigned int v = atomicAdd(&d_count, 1u);
        s_flag = (v == NCTA - 1) ? 1u : 0u;
    }
    __syncthreads();
    if (s_flag) {
        __threadfence();   // acquire: all CTAs' d_partial visible
        if (tid < NB*NO) {
            float s = 0.f;
            for (int i = 0; i < 64; i++) s += d_partial[tid*64 + i];
            float m = s * (1.0f / (float)NPIX);
            s_vals[tid] = m;
            if (1 + tid < out_size) out[1 + tid] = m;
        }
        __syncthreads();
        if (tid == 0) {
            float s = 0.f;
            #pragma unroll
            for (int i = 0; i < NB*NO; i++) s += s_vals[i];
            if (out_size > 0) out[0] = s / (float)(NB*NO);
            d_count = 0;   // reset for next graph replay
        }
    }
}

extern "C" void kernel_launch(void* const* d_in, const int* in_sizes, int n_in,
                              void* d_out, int out_size) {
    const float* outs = (const float*)d_in[0];
    const float* labs = (const float*)d_in[1];
    if (n_in >= 2 && in_sizes[0] < in_sizes[1]) {  // defensive: outputs is larger
        const float* tmp = outs; outs = labs; labs = tmp;
    }

    const int SMEM = SMEM_FLOATS * (int)sizeof(float);   // 230,688 B
    cudaFuncSetAttribute(fused_kernel, cudaFuncAttributeMaxDynamicSharedMemorySize, SMEM);
    fused_kernel<<<dim3(8, 8, NB), NT, SMEM>>>(outs, labs, (float*)d_out, out_size);
}